// round 6
// baseline (speedup 1.0000x reference)
#include <cuda_runtime.h>
#include <math.h>

#define TPB    288        // 9 warps; 288 threads, tid 0 also handles position 288
#define NPOS   289        // 17*17 core positions
#define TW     28         // padded tile width (27 rows x 28 cols)
#define TCELLS (27*28)

typedef unsigned long long u64;

#define ADD2(d,a,b)   asm("add.rn.f32x2 %0,%1,%2;"    : "=l"(d) : "l"(a), "l"(b))
#define MUL2(d,a,b)   asm("mul.rn.f32x2 %0,%1,%2;"    : "=l"(d) : "l"(a), "l"(b))
#define FMA2(d,a,b,c) asm("fma.rn.f32x2 %0,%1,%2,%3;" : "=l"(d) : "l"(a), "l"(b), "l"(c))
#define UNPK2(x,y,a)  asm("mov.b64 {%0,%1},%2;"       : "=f"(x), "=f"(y) : "l"(a))
#define LG2(d,s)      asm("lg2.approx.f32 %0,%1;"     : "=f"(d) : "f"(s))
#define EX2(d,s)      asm("ex2.approx.f32 %0,%1;"     : "=f"(d) : "f"(s))

// s^(5/6) via exp2(0.83333*log2 s); s==0 -> lg2=-Inf -> ex2=0 (matches guarded ref)
__device__ __forceinline__ float pow56(float s) {
    float l, r; LG2(l, s); l *= 0.8333333333f; EX2(r, l); return r;
}
// (sd/32)^(1/5) = exp2(0.2*log2(sd) - 1); sd==0 -> 0
__device__ __forceinline__ float pow15_div32(float sd) {
    float l, r; LG2(l, sd); l = fmaf(0.2f, l, -1.0f); EX2(r, l); return r;
}

__device__ __forceinline__ void compute_pos(const float2* __restrict__ g,
                                            const float2* __restrict__ nc6,
                                            int base, float& logit, float& dval)
{
    const u64 NC   = *(const u64*)&nc6[base];       // packed (-6x0,-6x1)
    const u64 Dc   = *(const u64*)&g[base];         // center cell, shared by all 4 lines
    const u64 NEG1 = 0xBF800000BF800000ULL;         // (-1,-1)
    const u64 AMSK = 0x7FFFFFFF7FFFFFFFULL;

    const int steps[4] = {1, TW, TW + 1, TW - 1};   // H, V, diag, anti-diag
    float sd0 = 0.f, sd1 = 0.f;

    #pragma unroll
    for (int o = 0; o < 4; ++o) {
        const int st = steps[o];
        u64 D0 = *(const u64*)&g[base - 4 * st];
        u64 D1 = *(const u64*)&g[base - 3 * st];
        u64 D2 = *(const u64*)&g[base - 2 * st];
        u64 D3 = *(const u64*)&g[base - 1 * st];
        u64 D5 = *(const u64*)&g[base + 1 * st];
        u64 D6 = *(const u64*)&g[base + 2 * st];
        u64 D7 = *(const u64*)&g[base + 3 * st];
        u64 D8 = *(const u64*)&g[base + 4 * st];

        u64 U;                               // packed sliding 5-window sum
        ADD2(U, Dc, D5); ADD2(U, U, D6); ADD2(U, U, D7); ADD2(U, U, D8);

        u64 S = 0ULL;                        // packed accum of (2*relu)^6
        #pragma unroll
        for (int q = 0; q < 5; ++q) {
            if (q == 1) { ADD2(U, U, D3); FMA2(U, D8, NEG1, U); }
            if (q == 2) { ADD2(U, U, D2); FMA2(U, D7, NEG1, U); }
            if (q == 3) { ADD2(U, U, D1); FMA2(U, D6, NEG1, U); }
            if (q == 4) { ADD2(U, U, D0); FMA2(U, D5, NEG1, U); }
            u64 R; ADD2(R, U, NC);           // r = W - 6*center (both streams)
            u64 A = R & AMSK;                // |r|
            u64 T; ADD2(T, R, A);            // 2*relu(r) exact
            u64 T2; MUL2(T2, T, T);
            u64 T4; MUL2(T4, T2, T2);
            FMA2(S, T4, T2, S);              // += (2relu)^6 = 64*relu^6
        }
        float s0, s1; UNPK2(s0, s1, S);
        sd0 += pow56(s0);                    // 64^(5/6)=32, folded into final /32
        sd1 += pow56(s1);
    }
    float f0 = pow15_div32(sd0);
    float f1 = pow15_div32(sd1);
    logit = f0 + f1;
    dval  = f0 - f1;
}

__global__ __launch_bounds__(TPB, 7)
void topo_kernel(const float* __restrict__ state, float* __restrict__ out, int nb)
{
    const int b   = blockIdx.x;
    const int tid = threadIdx.x;

    __shared__ float2 g[TCELLS];     // (g0,g1) channel-combined, zero halo
    __shared__ float2 nc6[TCELLS];   // (-6x0,-6x1), only core cells read
    __shared__ float  red[64];

    for (int i = tid; i < TCELLS; i += TPB) g[i] = make_float2(0.f, 0.f);
    __syncthreads();

    const float* sp = state + (size_t)b * 1083;
    for (int i = tid; i < 361; i += TPB) {
        int y = i / 19, x = i - y * 19;
        float x0 = sp[3 * i], x1 = sp[3 * i + 1], x2 = sp[3 * i + 2];
        int idx = (y + 4) * TW + (x + 4);
        g[idx]   = make_float2(fmaf(-5.f, x1 + x2, x0), fmaf(-5.f, x0 + x2, x1));
        nc6[idx] = make_float2(-6.f * x0, -6.f * x1);
    }
    __syncthreads();

    const int py = tid / 17;
    const int px = tid - py * 17;
    const int base = (py + 5) * TW + (px + 5);

    float logit, dval;
    compute_pos(g, nc6, base, logit, dval);

    float logit2 = -INFINITY, dval2 = 0.f;   // position 288, handled by tid 0
    if (tid == 0)
        compute_pos(g, nc6, 21 * TW + 21, logit2, dval2);

    const unsigned FULL = 0xffffffffu;
    const int wid  = tid >> 5;
    const int lane = tid & 31;

    // block max of logits
    float m = fmaxf(logit, logit2);
    #pragma unroll
    for (int off = 16; off; off >>= 1)
        m = fmaxf(m, __shfl_xor_sync(FULL, m, off));
    if (lane == 0) red[wid] = m;
    __syncthreads();
    if (tid < 32) {
        float t = (tid < TPB / 32) ? red[tid] : -INFINITY;
        #pragma unroll
        for (int off = 8; off; off >>= 1)
            t = fmaxf(t, __shfl_xor_sync(FULL, t, off));
        if (tid == 0) red[32] = t;
    }
    __syncthreads();
    const float maxv = red[32];

    // softmax denom + value-head sum
    float e  = __expf(2.f * (logit - maxv));                 // POLICY_STRETCH = 2
    float e2 = (tid == 0) ? __expf(2.f * (logit2 - maxv)) : 0.f;
    float se = e + e2, sv = dval + dval2;
    #pragma unroll
    for (int off = 16; off; off >>= 1) {
        se += __shfl_xor_sync(FULL, se, off);
        sv += __shfl_xor_sync(FULL, sv, off);
    }
    if (lane == 0) { red[wid] = se; red[wid + 16] = sv; }
    __syncthreads();
    if (tid < 32) {
        float a  = (tid < TPB / 32) ? red[tid] : 0.f;
        float bb = (tid < TPB / 32) ? red[tid + 16] : 0.f;
        #pragma unroll
        for (int off = 8; off; off >>= 1) {
            a  += __shfl_xor_sync(FULL, a, off);
            bb += __shfl_xor_sync(FULL, bb, off);
        }
        if (tid == 0) { red[33] = a; red[34] = bb; }
    }
    __syncthreads();

    const float denom = red[33];
    out[(size_t)b * NPOS + tid] = __fdividef(e, denom);
    if (tid == 0) {
        out[(size_t)b * NPOS + 288] = __fdividef(e2, denom);
        out[(size_t)nb * NPOS + b]  = tanhf(red[34] * (0.2f / 32.f)); // tanh(VS*VG*D)
    }
}

extern "C" void kernel_launch(void* const* d_in, const int* in_sizes, int n_in,
                              void* d_out, int out_size)
{
    const float* state = (const float*)d_in[0];
    const int nb = in_sizes[0] / (19 * 19 * 3);
    topo_kernel<<<nb, TPB>>>(state, (float*)d_out, nb);
}